// round 1
// baseline (speedup 1.0000x reference)
#include <cuda_runtime.h>
#include <math.h>

// ---------------------------------------------------------------------------
// Problem constants
// ---------------------------------------------------------------------------
#define BATCH      2048
#define TOKENS     8
#define MROWS      (BATCH * TOKENS)       // 16384
#define DIMT       1024
#define HIDT       4096
#define OUTT       1024
#define NHEADS     16
#define HEADD      64
#define ATT_SCALE  0.125f                 // 64^-0.5
#define LN_EPS     1e-5f

// ---------------------------------------------------------------------------
// Scratch (device globals: allocation-free per harness rules)
// ---------------------------------------------------------------------------
__device__ float g_Q[(long)MROWS * DIMT];   //  64 MB
__device__ float g_K[(long)MROWS * DIMT];   //  64 MB
__device__ float g_V[(long)MROWS * HIDT];   // 256 MB
__device__ float g_A[(long)MROWS * HIDT];   // 256 MB (post LN+swish activations)

// ---------------------------------------------------------------------------
// Generic fp32 GEMM:  C[M,N] = A[M,K] @ W[K,N] + bias[N]
// 128x128 tile, BK=16, 8x8 per-thread, double-buffered smem
// ---------------------------------------------------------------------------
#define BM 128
#define BN 128
#define BK 16
#define TM 8
#define TN 8

__global__ __launch_bounds__(256, 2)
void gemm_bias_kernel(const float* __restrict__ A, const float* __restrict__ W,
                      const float* __restrict__ bias, float* __restrict__ C,
                      int M, int N, int K)
{
    __shared__ float As[2][BK][BM + 4];
    __shared__ float Bs[2][BK][BN];

    const int tid = threadIdx.x;
    const long m0 = (long)blockIdx.y * BM;
    const int  n0 = blockIdx.x * BN;
    const int  tx = (tid & 15) * TN;   // 0..120
    const int  ty = (tid >> 4) * TM;   // 0..120

    // A tile: 128 rows x 4 float4s = 512 slots, 2 per thread
    const int aRow0 = tid >> 2;            // 0..63
    const int aRow1 = aRow0 + 64;          // 64..127
    const int aCol  = (tid & 3) << 2;      // 0,4,8,12
    // B tile: 16 rows x 32 float4s = 512 slots, 2 per thread
    const int bRow0 = tid >> 5;            // 0..7
    const int bRow1 = bRow0 + 8;           // 8..15
    const int bCol  = (tid & 31) << 2;     // 0..124

    const float* Ap = A + m0 * K;
    const float* Wp = W + n0;

    float4 a0, a1, b0, b1;

    auto fetch = [&](int k0) {
        a0 = *(const float4*)(Ap + (long)aRow0 * K + k0 + aCol);
        a1 = *(const float4*)(Ap + (long)aRow1 * K + k0 + aCol);
        b0 = *(const float4*)(Wp + (long)(k0 + bRow0) * N + bCol);
        b1 = *(const float4*)(Wp + (long)(k0 + bRow1) * N + bCol);
    };
    auto stash = [&](int buf) {
        As[buf][aCol + 0][aRow0] = a0.x;
        As[buf][aCol + 1][aRow0] = a0.y;
        As[buf][aCol + 2][aRow0] = a0.z;
        As[buf][aCol + 3][aRow0] = a0.w;
        As[buf][aCol + 0][aRow1] = a1.x;
        As[buf][aCol + 1][aRow1] = a1.y;
        As[buf][aCol + 2][aRow1] = a1.z;
        As[buf][aCol + 3][aRow1] = a1.w;
        *(float4*)&Bs[buf][bRow0][bCol] = b0;
        *(float4*)&Bs[buf][bRow1][bCol] = b1;
    };

    float acc[TM][TN];
    #pragma unroll
    for (int i = 0; i < TM; i++)
        #pragma unroll
        for (int j = 0; j < TN; j++) acc[i][j] = 0.0f;

    fetch(0);
    stash(0);
    __syncthreads();

    const int nk = K / BK;
    for (int kt = 0; kt < nk; kt++) {
        const int buf = kt & 1;
        if (kt + 1 < nk) fetch((kt + 1) * BK);

        #pragma unroll
        for (int k = 0; k < BK; k++) {
            float ra[TM], rb[TN];
            *(float4*)&ra[0] = *(const float4*)&As[buf][k][ty];
            *(float4*)&ra[4] = *(const float4*)&As[buf][k][ty + 4];
            *(float4*)&rb[0] = *(const float4*)&Bs[buf][k][tx];
            *(float4*)&rb[4] = *(const float4*)&Bs[buf][k][tx + 4];
            #pragma unroll
            for (int i = 0; i < TM; i++)
                #pragma unroll
                for (int j = 0; j < TN; j++)
                    acc[i][j] += ra[i] * rb[j];
        }

        if (kt + 1 < nk) stash(buf ^ 1);
        __syncthreads();
    }

    #pragma unroll
    for (int i = 0; i < TM; i++) {
        const long row = m0 + ty + i;
        #pragma unroll
        for (int j = 0; j < TN; j += 4) {
            float4 r;
            r.x = acc[i][j + 0] + bias[n0 + tx + j + 0];
            r.y = acc[i][j + 1] + bias[n0 + tx + j + 1];
            r.z = acc[i][j + 2] + bias[n0 + tx + j + 2];
            r.w = acc[i][j + 3] + bias[n0 + tx + j + 3];
            *(float4*)&C[row * N + n0 + tx + j] = r;
        }
    }
}

// ---------------------------------------------------------------------------
// Fused attention + talking heads + softmax + attn@V + LayerNorm + swish.
// One block per batch element b (2048 blocks, 256 threads).
// Dynamic smem: q_s[8][1024] + k_s[8][1024] = 64 KB.
// ---------------------------------------------------------------------------
__global__ __launch_bounds__(256, 1)
void attn_ln_kernel(const float* __restrict__ Q, const float* __restrict__ Km,
                    const float* __restrict__ V,
                    const float* __restrict__ Wl, const float* __restrict__ bl,
                    const float* __restrict__ Ww, const float* __restrict__ bw,
                    const float* __restrict__ gamma, const float* __restrict__ beta,
                    float* __restrict__ Aout)
{
    extern __shared__ float dyn[];
    float* q_s = dyn;           // 8192
    float* k_s = dyn + 8192;    // 8192

    __shared__ float s_s[NHEADS][TOKENS][TOKENS];  // raw scores
    __shared__ float t_s[NHEADS][TOKENS][TOKENS];  // mixed / softmaxed
    __shared__ float u_s[NHEADS][TOKENS][TOKENS];  // post-mix attn weights
    __shared__ float wl_s[256], ww_s[256], bl_s[16], bw_s[16];
    __shared__ float red[TOKENS][256];
    __shared__ float mean_s[TOKENS], rstd_s[TOKENS];

    const int b   = blockIdx.x;
    const int tid = threadIdx.x;
    const long rowbase = (long)b * TOKENS;

    // stage Q, K rows for this batch + head-mix weights
    {
        const long base = rowbase * DIMT;
        for (int i = tid; i < TOKENS * DIMT; i += 256) {
            q_s[i] = Q[base + i];
            k_s[i] = Km[base + i];
        }
        wl_s[tid] = Wl[tid];
        ww_s[tid] = Ww[tid];
        if (tid < 16) { bl_s[tid] = bl[tid]; bw_s[tid] = bw[tid]; }
    }
    __syncthreads();

    // scores: s[h][n][m] = SCALE * <q[n,h,:], k[m,h,:]>   (1024 entries, 4/thread)
    #pragma unroll
    for (int r = 0; r < 4; r++) {
        const int e = tid + r * 256;
        const int h = e >> 6;
        const int n = (e >> 3) & 7;
        const int m = e & 7;
        const float* qp = q_s + n * DIMT + h * HEADD;
        const float* kp = k_s + m * DIMT + h * HEADD;
        float d = 0.0f;
        #pragma unroll
        for (int t = 0; t < HEADD; t++) d += qp[t] * kp[t];
        s_s[h][n][m] = d * ATT_SCALE;
    }
    __syncthreads();

    // talking-heads mix #1: t[g][n][m] = bl[g] + sum_h s[h][n][m] * Wl[h][g]
    #pragma unroll
    for (int r = 0; r < 4; r++) {
        const int e = tid + r * 256;
        const int g = e >> 6;
        const int n = (e >> 3) & 7;
        const int m = e & 7;
        float acc = bl_s[g];
        #pragma unroll
        for (int h = 0; h < NHEADS; h++) acc += s_s[h][n][m] * wl_s[h * 16 + g];
        t_s[g][n][m] = acc;
    }
    __syncthreads();

    // softmax over m for each of the 128 (g,n) rows
    if (tid < 128) {
        const int g = tid >> 3;
        const int n = tid & 7;
        float mx = t_s[g][n][0];
        #pragma unroll
        for (int m = 1; m < TOKENS; m++) mx = fmaxf(mx, t_s[g][n][m]);
        float e[TOKENS], sum = 0.0f;
        #pragma unroll
        for (int m = 0; m < TOKENS; m++) { e[m] = expf(t_s[g][n][m] - mx); sum += e[m]; }
        const float inv = 1.0f / sum;
        #pragma unroll
        for (int m = 0; m < TOKENS; m++) t_s[g][n][m] = e[m] * inv;
    }
    __syncthreads();

    // talking-heads mix #2: u[g][n][m] = bw[g] + sum_h p[h][n][m] * Ww[h][g]
    #pragma unroll
    for (int r = 0; r < 4; r++) {
        const int e = tid + r * 256;
        const int g = e >> 6;
        const int n = (e >> 3) & 7;
        const int m = e & 7;
        float acc = bw_s[g];
        #pragma unroll
        for (int h = 0; h < NHEADS; h++) acc += t_s[h][n][m] * ww_s[h * 16 + g];
        u_s[g][n][m] = acc;
    }
    __syncthreads();

    // o[n][c] = sum_m u[head(c)][n][m] * V[b,m,c]; thread owns c = j*256 + tid,
    // j = 0..15 == head index for that 256-wide chunk.
    float acc[TOKENS][16];
    #pragma unroll
    for (int n = 0; n < TOKENS; n++)
        #pragma unroll
        for (int j = 0; j < 16; j++) acc[n][j] = 0.0f;

    const float* Vb = V + rowbase * HIDT;
    #pragma unroll
    for (int m = 0; m < TOKENS; m++) {
        #pragma unroll
        for (int j = 0; j < 16; j++) {
            const float vv = Vb[(long)m * HIDT + j * 256 + tid];
            #pragma unroll
            for (int n = 0; n < TOKENS; n++)
                acc[n][j] += u_s[j][n][m] * vv;
        }
    }

    // LayerNorm over HIDT per token row, then swish, then store.
    // mean
    #pragma unroll
    for (int n = 0; n < TOKENS; n++) {
        float p = 0.0f;
        #pragma unroll
        for (int j = 0; j < 16; j++) p += acc[n][j];
        red[n][tid] = p;
    }
    __syncthreads();
    if (tid < TOKENS) {
        float s0 = 0.f, s1 = 0.f, s2 = 0.f, s3 = 0.f;
        #pragma unroll 4
        for (int t = 0; t < 256; t += 4) {
            s0 += red[tid][t + 0]; s1 += red[tid][t + 1];
            s2 += red[tid][t + 2]; s3 += red[tid][t + 3];
        }
        mean_s[tid] = (s0 + s1 + s2 + s3) * (1.0f / HIDT);
    }
    __syncthreads();
    // variance
    #pragma unroll
    for (int n = 0; n < TOKENS; n++) {
        const float mu = mean_s[n];
        float p = 0.0f;
        #pragma unroll
        for (int j = 0; j < 16; j++) { const float d = acc[n][j] - mu; p += d * d; }
        red[n][tid] = p;
    }
    __syncthreads();
    if (tid < TOKENS) {
        float s0 = 0.f, s1 = 0.f, s2 = 0.f, s3 = 0.f;
        #pragma unroll 4
        for (int t = 0; t < 256; t += 4) {
            s0 += red[tid][t + 0]; s1 += red[tid][t + 1];
            s2 += red[tid][t + 2]; s3 += red[tid][t + 3];
        }
        const float var = (s0 + s1 + s2 + s3) * (1.0f / HIDT);
        rstd_s[tid] = rsqrtf(var + LN_EPS);
    }
    __syncthreads();
    // normalize + swish + write
    #pragma unroll
    for (int n = 0; n < TOKENS; n++) {
        const float mu = mean_s[n];
        const float rs = rstd_s[n];
        float* dst = Aout + (rowbase + n) * HIDT;
        #pragma unroll
        for (int j = 0; j < 16; j++) {
            const int c = j * 256 + tid;
            const float y = (acc[n][j] - mu) * rs * gamma[c] + beta[c];
            dst[c] = y / (1.0f + expf(-y));   // y * sigmoid(y)
        }
    }
}

// ---------------------------------------------------------------------------
// Launch
// ---------------------------------------------------------------------------
extern "C" void kernel_launch(void* const* d_in, const int* in_sizes, int n_in,
                              void* d_out, int out_size)
{
    const float* x     = (const float*)d_in[0];
    const float* Wq    = (const float*)d_in[1];
    const float* bq    = (const float*)d_in[2];
    const float* Wk    = (const float*)d_in[3];
    const float* bk    = (const float*)d_in[4];
    const float* Wv    = (const float*)d_in[5];
    const float* bv    = (const float*)d_in[6];
    const float* Wl    = (const float*)d_in[7];
    const float* bl    = (const float*)d_in[8];
    const float* Ww    = (const float*)d_in[9];
    const float* bw    = (const float*)d_in[10];
    const float* gamma = (const float*)d_in[11];
    const float* beta  = (const float*)d_in[12];
    const float* Wp    = (const float*)d_in[13];
    const float* bp    = (const float*)d_in[14];
    float* out = (float*)d_out;

    float *qb, *kb, *vb, *ab;
    cudaGetSymbolAddress((void**)&qb, g_Q);
    cudaGetSymbolAddress((void**)&kb, g_K);
    cudaGetSymbolAddress((void**)&vb, g_V);
    cudaGetSymbolAddress((void**)&ab, g_A);

    cudaFuncSetAttribute(attn_ln_kernel,
                         cudaFuncAttributeMaxDynamicSharedMemorySize, 64 * 1024);

    dim3 blk(256);
    // Q = x @ Wq + bq
    gemm_bias_kernel<<<dim3(DIMT / BN, MROWS / BM), blk>>>(x, Wq, bq, qb, MROWS, DIMT, DIMT);
    // K = x @ Wk + bk
    gemm_bias_kernel<<<dim3(DIMT / BN, MROWS / BM), blk>>>(x, Wk, bk, kb, MROWS, DIMT, DIMT);
    // V = x @ Wv + bv
    gemm_bias_kernel<<<dim3(HIDT / BN, MROWS / BM), blk>>>(x, Wv, bv, vb, MROWS, HIDT, DIMT);
    // attention + talking heads + softmax + attn@V + LayerNorm + swish
    attn_ln_kernel<<<BATCH, 256, 64 * 1024>>>(qb, kb, vb, Wl, bl, Ww, bw, gamma, beta, ab);
    // out = a @ Wp + bp
    gemm_bias_kernel<<<dim3(OUTT / BN, MROWS / BM), blk>>>(ab, Wp, bp, out, MROWS, OUTT, HIDT);
}

// round 3
// speedup vs baseline: 2.5921x; 2.5921x over previous
#include <cuda_runtime.h>
#include <math.h>
#include <stdint.h>

// ---------------------------------------------------------------------------
// Problem constants
// ---------------------------------------------------------------------------
#define BATCH      2048
#define TOKENS     8
#define MROWS      (BATCH * TOKENS)       // 16384
#define DIMT       1024
#define HIDT       4096
#define OUTT       1024
#define NHEADS     16
#define HEADD      64
#define ATT_SCALE  0.125f
#define LN_EPS     1e-5f

// ---------------------------------------------------------------------------
// Scratch (device globals)
// ---------------------------------------------------------------------------
__device__ float g_Q[(long)MROWS * DIMT];
__device__ float g_K[(long)MROWS * DIMT];
__device__ float g_V[(long)MROWS * HIDT];
__device__ float g_A[(long)MROWS * HIDT];

// ---------------------------------------------------------------------------
// Helpers
// ---------------------------------------------------------------------------
__device__ __forceinline__ uint32_t smem_u32(const void* p) {
    uint32_t a;
    asm("{ .reg .u64 t; cvta.to.shared.u64 t, %1; cvt.u32.u64 %0, t; }" : "=r"(a) : "l"(p));
    return a;
}
__device__ __forceinline__ void cp_async16(uint32_t dst, const void* src) {
    asm volatile("cp.async.cg.shared.global [%0], [%1], 16;" :: "r"(dst), "l"(src));
}
__device__ __forceinline__ uint32_t f2tf32(float f) {
    uint32_t t;
    asm("cvt.rna.tf32.f32 %0, %1;" : "=r"(t) : "f"(f));
    return t;
}
__device__ __forceinline__ void mma_tf32(float* d, const uint32_t* a, const uint32_t* b) {
    asm volatile("mma.sync.aligned.m16n8k8.row.col.f32.tf32.tf32.f32 "
        "{%0,%1,%2,%3}, {%4,%5,%6,%7}, {%8,%9}, {%0,%1,%2,%3};"
        : "+f"(d[0]), "+f"(d[1]), "+f"(d[2]), "+f"(d[3])
        : "r"(a[0]), "r"(a[1]), "r"(a[2]), "r"(a[3]), "r"(b[0]), "r"(b[1]));
}

// ---------------------------------------------------------------------------
// tf32 mma.sync GEMM: C[M,N] = A[M,K] @ W[K,N] + bias[N]
// CTA tile 128x128, BK=32, 8 warps (2x4 grid of 64x32 warp tiles),
// 4-stage cp.async pipeline.
// SMEM per stage: A[128][36] (pad 4) + B[32][132] (pad 4) floats.
// ---------------------------------------------------------------------------
#define GBM 128
#define GBN 128
#define KC  32
#define A_STRIDE 36
#define B_STRIDE 132
#define A_ST_FLOATS (GBM * A_STRIDE)            // 4608
#define STAGE_FLOATS (A_ST_FLOATS + KC * B_STRIDE) // 8832
#define STAGE_BYTES (STAGE_FLOATS * 4)          // 35328
#define GEMM_SMEM (4 * STAGE_BYTES)             // 141312

__global__ __launch_bounds__(256, 1)
void gemm_tc(const float* __restrict__ A, const float* __restrict__ W,
             const float* __restrict__ bias, float* __restrict__ C,
             int N, int K)
{
    extern __shared__ __align__(16) float smf[];
    const int tid  = threadIdx.x;
    const int wid  = tid >> 5;
    const int lane = tid & 31;
    const int lr = lane >> 2;       // 0..7
    const int lc = lane & 3;        // 0..3
    const int wm = (wid >> 2) * 64; // 0 | 64
    const int wn = (wid & 3) * 32;  // 0,32,64,96
    const long m0 = (long)blockIdx.y * GBM;
    const long n0 = (long)blockIdx.x * GBN;
    const int NK = K / KC;

    const uint32_t sbase = smem_u32(smf);

    auto load_stage = [&](int s, int kt) {
        const uint32_t abase = sbase + s * STAGE_BYTES;
        const uint32_t bbase = abase + A_ST_FLOATS * 4;
        const float* ag = A + m0 * K + (long)kt * KC;
        const float* bg = W + (long)kt * KC * N + n0;
        #pragma unroll
        for (int i = 0; i < 4; i++) {            // A: 128 rows x 8 float4
            const int u = tid + i * 256, r = u >> 3, c = u & 7;
            cp_async16(abase + r * (A_STRIDE * 4) + c * 16, ag + (long)r * K + c * 4);
        }
        #pragma unroll
        for (int i = 0; i < 4; i++) {            // B: 32 rows x 32 float4
            const int u = tid + i * 256, r = u >> 5, c = u & 31;
            cp_async16(bbase + r * (B_STRIDE * 4) + c * 16, bg + (long)r * N + c * 4);
        }
        asm volatile("cp.async.commit_group;" ::: "memory");
    };

    float d[4][4][4];
    #pragma unroll
    for (int mi = 0; mi < 4; mi++)
        #pragma unroll
        for (int ni = 0; ni < 4; ni++)
            #pragma unroll
            for (int r = 0; r < 4; r++) d[mi][ni][r] = 0.0f;

    load_stage(0, 0);
    load_stage(1, 1);
    load_stage(2, 2);

    for (int kt = 0; kt < NK; kt++) {
        const int s = kt & 3;
        asm volatile("cp.async.wait_group 2;" ::: "memory");
        __syncthreads();

        const float* As = smf + s * STAGE_FLOATS;
        const float* Bs = As + A_ST_FLOATS;
        #pragma unroll
        for (int k0 = 0; k0 < KC; k0 += 8) {
            uint32_t af[4][4], bf[4][2];
            #pragma unroll
            for (int mi = 0; mi < 4; mi++) {
                const int r = wm + mi * 16 + lr;
                af[mi][0] = f2tf32(As[r * A_STRIDE + k0 + lc]);
                af[mi][1] = f2tf32(As[(r + 8) * A_STRIDE + k0 + lc]);
                af[mi][2] = f2tf32(As[r * A_STRIDE + k0 + lc + 4]);
                af[mi][3] = f2tf32(As[(r + 8) * A_STRIDE + k0 + lc + 4]);
            }
            #pragma unroll
            for (int ni = 0; ni < 4; ni++) {
                const int cn = wn + ni * 8 + lr;
                bf[ni][0] = f2tf32(Bs[(k0 + lc) * B_STRIDE + cn]);
                bf[ni][1] = f2tf32(Bs[(k0 + lc + 4) * B_STRIDE + cn]);
            }
            #pragma unroll
            for (int mi = 0; mi < 4; mi++)
                #pragma unroll
                for (int ni = 0; ni < 4; ni++)
                    mma_tf32(d[mi][ni], af[mi], bf[ni]);
        }

        if (kt + 3 < NK) load_stage((kt + 3) & 3, kt + 3);
        else             asm volatile("cp.async.commit_group;" ::: "memory");
    }

    // Epilogue: bias add + store
    #pragma unroll
    for (int mi = 0; mi < 4; mi++) {
        const long r0 = m0 + wm + mi * 16 + lr;
        #pragma unroll
        for (int ni = 0; ni < 4; ni++) {
            const int c0 = (int)n0 + wn + ni * 8 + 2 * lc;
            const float b0 = bias[c0], b1 = bias[c0 + 1];
            float2 v0 = make_float2(d[mi][ni][0] + b0, d[mi][ni][1] + b1);
            float2 v1 = make_float2(d[mi][ni][2] + b0, d[mi][ni][3] + b1);
            *(float2*)&C[r0 * N + c0] = v0;
            *(float2*)&C[(r0 + 8) * N + c0] = v1;
        }
    }
}

// ---------------------------------------------------------------------------
// Fused attention + talking heads + softmax + attn@V + LayerNorm + swish.
// One block per batch element, 512 threads.
// ---------------------------------------------------------------------------
__global__ __launch_bounds__(512, 1)
void attn_ln_kernel(const float* __restrict__ Q, const float* __restrict__ Km,
                    const float* __restrict__ V,
                    const float* __restrict__ Wl, const float* __restrict__ bl,
                    const float* __restrict__ Ww, const float* __restrict__ bw,
                    const float* __restrict__ gamma, const float* __restrict__ beta,
                    float* __restrict__ Aout)
{
    extern __shared__ float dyn[];
    float* q_s = dyn;
    float* k_s = dyn + 8192;

    __shared__ float s_s[NHEADS][TOKENS][TOKENS];
    __shared__ float t_s[NHEADS][TOKENS][TOKENS];
    __shared__ float u_s[NHEADS][TOKENS][TOKENS];
    __shared__ float wl_s[256], ww_s[256], bl_s[16], bw_s[16];
    __shared__ float red[TOKENS][512];
    __shared__ float mean_s[TOKENS], rstd_s[TOKENS];

    const int b   = blockIdx.x;
    const int tid = threadIdx.x;
    const long rowbase = (long)b * TOKENS;

    {
        const long base = rowbase * DIMT;
        for (int i = tid; i < TOKENS * DIMT; i += 512) {
            q_s[i] = Q[base + i];
            k_s[i] = Km[base + i];
        }
        if (tid < 256) { wl_s[tid] = Wl[tid]; ww_s[tid] = Ww[tid]; }
        if (tid < 16)  { bl_s[tid] = bl[tid]; bw_s[tid] = bw[tid]; }
    }
    __syncthreads();

    #pragma unroll
    for (int r = 0; r < 2; r++) {
        const int e = tid + r * 512;
        const int h = e >> 6, n = (e >> 3) & 7, m = e & 7;
        const float* qp = q_s + n * DIMT + h * HEADD;
        const float* kp = k_s + m * DIMT + h * HEADD;
        float dd = 0.0f;
        #pragma unroll
        for (int t = 0; t < HEADD; t++) dd += qp[t] * kp[t];
        s_s[h][n][m] = dd * ATT_SCALE;
    }
    __syncthreads();

    #pragma unroll
    for (int r = 0; r < 2; r++) {
        const int e = tid + r * 512;
        const int g = e >> 6, n = (e >> 3) & 7, m = e & 7;
        float acc = bl_s[g];
        #pragma unroll
        for (int h = 0; h < NHEADS; h++) acc += s_s[h][n][m] * wl_s[h * 16 + g];
        t_s[g][n][m] = acc;
    }
    __syncthreads();

    if (tid < 128) {
        const int g = tid >> 3, n = tid & 7;
        float mx = t_s[g][n][0];
        #pragma unroll
        for (int m = 1; m < TOKENS; m++) mx = fmaxf(mx, t_s[g][n][m]);
        float e[TOKENS], sum = 0.0f;
        #pragma unroll
        for (int m = 0; m < TOKENS; m++) { e[m] = expf(t_s[g][n][m] - mx); sum += e[m]; }
        const float inv = 1.0f / sum;
        #pragma unroll
        for (int m = 0; m < TOKENS; m++) t_s[g][n][m] = e[m] * inv;
    }
    __syncthreads();

    #pragma unroll
    for (int r = 0; r < 2; r++) {
        const int e = tid + r * 512;
        const int g = e >> 6, n = (e >> 3) & 7, m = e & 7;
        float acc = bw_s[g];
        #pragma unroll
        for (int h = 0; h < NHEADS; h++) acc += t_s[h][n][m] * ww_s[h * 16 + g];
        u_s[g][n][m] = acc;
    }
    __syncthreads();

    // o[n][c], c = j*512 + tid, head = c >> 8 = 2j + (tid >> 8)
    float acc[TOKENS][8];
    #pragma unroll
    for (int n = 0; n < TOKENS; n++)
        #pragma unroll
        for (int j = 0; j < 8; j++) acc[n][j] = 0.0f;

    const float* Vb = V + rowbase * HIDT;
    const int hoff = tid >> 8;
    #pragma unroll
    for (int m = 0; m < TOKENS; m++) {
        #pragma unroll
        for (int j = 0; j < 8; j++) {
            const float vv = Vb[(long)m * HIDT + j * 512 + tid];
            const int hh = 2 * j + hoff;
            #pragma unroll
            for (int n = 0; n < TOKENS; n++)
                acc[n][j] += u_s[hh][n][m] * vv;
        }
    }

    #pragma unroll
    for (int n = 0; n < TOKENS; n++) {
        float p = 0.0f;
        #pragma unroll
        for (int j = 0; j < 8; j++) p += acc[n][j];
        red[n][tid] = p;
    }
    __syncthreads();
    if (tid < TOKENS) {
        float s0 = 0.f, s1 = 0.f, s2 = 0.f, s3 = 0.f;
        #pragma unroll 4
        for (int t = 0; t < 512; t += 4) {
            s0 += red[tid][t + 0]; s1 += red[tid][t + 1];
            s2 += red[tid][t + 2]; s3 += red[tid][t + 3];
        }
        mean_s[tid] = (s0 + s1 + s2 + s3) * (1.0f / HIDT);
    }
    __syncthreads();
    #pragma unroll
    for (int n = 0; n < TOKENS; n++) {
        const float mu = mean_s[n];
        float p = 0.0f;
        #pragma unroll
        for (int j = 0; j < 8; j++) { const float dd = acc[n][j] - mu; p += dd * dd; }
        red[n][tid] = p;
    }
    __syncthreads();
    if (tid < TOKENS) {
        float s0 = 0.f, s1 = 0.f, s2 = 0.f, s3 = 0.f;
        #pragma unroll 4
        for (int t = 0; t < 512; t += 4) {
            s0 += red[tid][t + 0]; s1 += red[tid][t + 1];
            s2 += red[tid][t + 2]; s3 += red[tid][t + 3];
        }
        const float var = (s0 + s1 + s2 + s3) * (1.0f / HIDT);
        rstd_s[tid] = rsqrtf(var + LN_EPS);
    }
    __syncthreads();
    #pragma unroll
    for (int n = 0; n < TOKENS; n++) {
        const float mu = mean_s[n];
        const float rs = rstd_s[n];
        float* dst = Aout + (rowbase + n) * HIDT;
        #pragma unroll
        for (int j = 0; j < 8; j++) {
            const int c = j * 512 + tid;
            const float y = (acc[n][j] - mu) * rs * gamma[c] + beta[c];
            dst[c] = y / (1.0f + expf(-y));
        }
    }
}

// ---------------------------------------------------------------------------
// Launch
// ---------------------------------------------------------------------------
extern "C" void kernel_launch(void* const* d_in, const int* in_sizes, int n_in,
                              void* d_out, int out_size)
{
    const float* x     = (const float*)d_in[0];
    const float* Wq    = (const float*)d_in[1];
    const float* bq    = (const float*)d_in[2];
    const float* Wk    = (const float*)d_in[3];
    const float* bk    = (const float*)d_in[4];
    const float* Wv    = (const float*)d_in[5];
    const float* bv    = (const float*)d_in[6];
    const float* Wl    = (const float*)d_in[7];
    const float* bl    = (const float*)d_in[8];
    const float* Ww    = (const float*)d_in[9];
    const float* bw    = (const float*)d_in[10];
    const float* gamma = (const float*)d_in[11];
    const float* beta  = (const float*)d_in[12];
    const float* Wp    = (const float*)d_in[13];
    const float* bp    = (const float*)d_in[14];
    float* out = (float*)d_out;

    float *qb, *kb, *vb, *ab;
    cudaGetSymbolAddress((void**)&qb, g_Q);
    cudaGetSymbolAddress((void**)&kb, g_K);
    cudaGetSymbolAddress((void**)&vb, g_V);
    cudaGetSymbolAddress((void**)&ab, g_A);

    cudaFuncSetAttribute(gemm_tc, cudaFuncAttributeMaxDynamicSharedMemorySize, GEMM_SMEM);
    cudaFuncSetAttribute(attn_ln_kernel, cudaFuncAttributeMaxDynamicSharedMemorySize, 64 * 1024);

    gemm_tc<<<dim3(DIMT / GBN, MROWS / GBM), 256, GEMM_SMEM>>>(x, Wq, bq, qb, DIMT, DIMT);
    gemm_tc<<<dim3(DIMT / GBN, MROWS / GBM), 256, GEMM_SMEM>>>(x, Wk, bk, kb, DIMT, DIMT);
    gemm_tc<<<dim3(HIDT / GBN, MROWS / GBM), 256, GEMM_SMEM>>>(x, Wv, bv, vb, HIDT, DIMT);

    attn_ln_kernel<<<BATCH, 512, 64 * 1024>>>(qb, kb, vb, Wl, bl, Ww, bw, gamma, beta, ab);

    gemm_tc<<<dim3(OUTT / GBN, MROWS / GBM), 256, GEMM_SMEM>>>(ab, Wp, bp, out, OUTT, HIDT);
}

// round 4
// speedup vs baseline: 3.5985x; 1.3883x over previous
#include <cuda_runtime.h>
#include <math.h>
#include <stdint.h>

// ---------------------------------------------------------------------------
// Problem constants
// ---------------------------------------------------------------------------
#define BATCH      2048
#define TOKENS     8
#define MROWS      (BATCH * TOKENS)       // 16384
#define DIMT       1024
#define HIDT       4096
#define OUTT       1024
#define NHEADS     16
#define HEADD      64
#define ATT_SCALE  0.125f
#define LN_EPS     1e-5f

// ---------------------------------------------------------------------------
// Scratch (device globals)
// ---------------------------------------------------------------------------
__device__ float g_Q[(long)MROWS * DIMT];
__device__ float g_K[(long)MROWS * DIMT];
__device__ float g_V[(long)MROWS * HIDT];
__device__ float g_A[(long)MROWS * HIDT];

// ---------------------------------------------------------------------------
// Helpers
// ---------------------------------------------------------------------------
__device__ __forceinline__ uint32_t smem_u32(const void* p) {
    uint32_t a;
    asm("{ .reg .u64 t; cvta.to.shared.u64 t, %1; cvt.u32.u64 %0, t; }" : "=r"(a) : "l"(p));
    return a;
}
__device__ __forceinline__ void cp_async16(uint32_t dst, const void* src) {
    asm volatile("cp.async.cg.shared.global [%0], [%1], 16;" :: "r"(dst), "l"(src));
}
__device__ __forceinline__ uint32_t f2tf32(float f) {
    uint32_t t;
    asm("cvt.rna.tf32.f32 %0, %1;" : "=r"(t) : "f"(f));
    return t;
}
__device__ __forceinline__ void mma_tf32(float* d, const uint32_t* a, const uint32_t* b) {
    asm volatile("mma.sync.aligned.m16n8k8.row.col.f32.tf32.tf32.f32 "
        "{%0,%1,%2,%3}, {%4,%5,%6,%7}, {%8,%9}, {%0,%1,%2,%3};"
        : "+f"(d[0]), "+f"(d[1]), "+f"(d[2]), "+f"(d[3])
        : "r"(a[0]), "r"(a[1]), "r"(a[2]), "r"(a[3]), "r"(b[0]), "r"(b[1]));
}

// ---------------------------------------------------------------------------
// tf32 mma.sync GEMM: C[M,N] = A[M,K] @ W[K,N] + bias[N]
// CTA tile 128x128, BK=32, 8 warps (2x4 grid of 64x32 warp tiles),
// 3-stage cp.async pipeline, 2 CTAs/SM.
// SMEM per stage: A[128][36] + B[32][136] floats (both conflict-free).
// ---------------------------------------------------------------------------
#define GBM 128
#define GBN 128
#define KC  32
#define A_STRIDE 36
#define B_STRIDE 136
#define A_ST_FLOATS (GBM * A_STRIDE)                 // 4608
#define STAGE_FLOATS (A_ST_FLOATS + KC * B_STRIDE)   // 8960
#define STAGE_BYTES (STAGE_FLOATS * 4)               // 35840
#define GEMM_SMEM (3 * STAGE_BYTES)                  // 107520

__global__ __launch_bounds__(256, 2)
void gemm_tc(const float* __restrict__ A, const float* __restrict__ W,
             const float* __restrict__ bias, float* __restrict__ C,
             int N, int K)
{
    extern __shared__ __align__(16) float smf[];
    const int tid  = threadIdx.x;
    const int wid  = tid >> 5;
    const int lane = tid & 31;
    const int lr = lane >> 2;       // 0..7
    const int lc = lane & 3;        // 0..3
    const int wm = (wid >> 2) * 64; // 0 | 64
    const int wn = (wid & 3) * 32;  // 0,32,64,96
    const long m0 = (long)blockIdx.y * GBM;
    const long n0 = (long)blockIdx.x * GBN;
    const int NK = K / KC;

    const uint32_t sbase = smem_u32(smf);

    auto load_stage = [&](int s, int kt) {
        const uint32_t abase = sbase + s * STAGE_BYTES;
        const uint32_t bbase = abase + A_ST_FLOATS * 4;
        const float* ag = A + m0 * K + (long)kt * KC;
        const float* bg = W + (long)kt * KC * N + n0;
        #pragma unroll
        for (int i = 0; i < 4; i++) {            // A: 128 rows x 8 float4
            const int u = tid + i * 256, r = u >> 3, c = u & 7;
            cp_async16(abase + r * (A_STRIDE * 4) + c * 16, ag + (long)r * K + c * 4);
        }
        #pragma unroll
        for (int i = 0; i < 4; i++) {            // B: 32 rows x 32 float4
            const int u = tid + i * 256, r = u >> 5, c = u & 31;
            cp_async16(bbase + r * (B_STRIDE * 4) + c * 16, bg + (long)r * N + c * 4);
        }
        asm volatile("cp.async.commit_group;" ::: "memory");
    };

    float d[4][4][4];
    #pragma unroll
    for (int mi = 0; mi < 4; mi++)
        #pragma unroll
        for (int ni = 0; ni < 4; ni++)
            #pragma unroll
            for (int r = 0; r < 4; r++) d[mi][ni][r] = 0.0f;

    load_stage(0, 0);
    load_stage(1, 1);

    int s = 0;
    for (int kt = 0; kt < NK; kt++) {
        asm volatile("cp.async.wait_group 1;" ::: "memory");
        __syncthreads();

        const float* As = smf + s * STAGE_FLOATS;
        const float* Bs = As + A_ST_FLOATS;
        #pragma unroll
        for (int k0 = 0; k0 < KC; k0 += 8) {
            uint32_t af[4][4], bf[4][2];
            #pragma unroll
            for (int mi = 0; mi < 4; mi++) {
                const int r = wm + mi * 16 + lr;
                af[mi][0] = f2tf32(As[r * A_STRIDE + k0 + lc]);
                af[mi][1] = f2tf32(As[(r + 8) * A_STRIDE + k0 + lc]);
                af[mi][2] = f2tf32(As[r * A_STRIDE + k0 + lc + 4]);
                af[mi][3] = f2tf32(As[(r + 8) * A_STRIDE + k0 + lc + 4]);
            }
            #pragma unroll
            for (int ni = 0; ni < 4; ni++) {
                const int cn = wn + ni * 8 + lr;
                bf[ni][0] = f2tf32(Bs[(k0 + lc) * B_STRIDE + cn]);
                bf[ni][1] = f2tf32(Bs[(k0 + lc + 4) * B_STRIDE + cn]);
            }
            #pragma unroll
            for (int mi = 0; mi < 4; mi++)
                #pragma unroll
                for (int ni = 0; ni < 4; ni++)
                    mma_tf32(d[mi][ni], af[mi], bf[ni]);
        }
        __syncthreads();

        if (kt + 2 < NK) load_stage((s + 2) % 3, kt + 2);
        else             asm volatile("cp.async.commit_group;" ::: "memory");
        s = (s + 1) % 3;
    }

    // Epilogue: bias add + store
    #pragma unroll
    for (int mi = 0; mi < 4; mi++) {
        const long r0 = m0 + wm + mi * 16 + lr;
        #pragma unroll
        for (int ni = 0; ni < 4; ni++) {
            const int c0 = (int)n0 + wn + ni * 8 + 2 * lc;
            const float b0 = bias[c0], b1 = bias[c0 + 1];
            float2 v0 = make_float2(d[mi][ni][0] + b0, d[mi][ni][1] + b1);
            float2 v1 = make_float2(d[mi][ni][2] + b0, d[mi][ni][3] + b1);
            *(float2*)&C[r0 * N + c0] = v0;
            *(float2*)&C[(r0 + 8) * N + c0] = v1;
        }
    }
}

// ---------------------------------------------------------------------------
// Fused attention + talking heads + softmax + attn@V + LayerNorm + swish.
// One block per batch element, 1024 threads; each thread owns 4 consecutive
// columns of HIDT (c = 4*tid), all within one head.
// ---------------------------------------------------------------------------
#define QK_STRIDE 1028    // pad to kill 8-way bank conflicts in score phase

__global__ __launch_bounds__(1024, 1)
void attn_ln_kernel(const float* __restrict__ Q, const float* __restrict__ Km,
                    const float* __restrict__ V,
                    const float* __restrict__ Wl, const float* __restrict__ bl,
                    const float* __restrict__ Ww, const float* __restrict__ bw,
                    const float* __restrict__ gamma, const float* __restrict__ beta,
                    float* __restrict__ Aout)
{
    extern __shared__ float dyn[];
    float* q_s = dyn;                        // 8 * 1028
    float* k_s = dyn + TOKENS * QK_STRIDE;   // 8 * 1028

    __shared__ float s_s[NHEADS][TOKENS][TOKENS];
    __shared__ float t_s[NHEADS][TOKENS][TOKENS];
    __shared__ float u_s[NHEADS][TOKENS][TOKENS];
    __shared__ float wl_s[256], ww_s[256], bl_s[16], bw_s[16];
    __shared__ float red[TOKENS][32];
    __shared__ float mean_s[TOKENS], rstd_s[TOKENS];

    const int b    = blockIdx.x;
    const int tid  = threadIdx.x;
    const int lane = tid & 31;
    const int wrp  = tid >> 5;
    const long rowbase = (long)b * TOKENS;

    {
        const long base = rowbase * DIMT;
        for (int i = tid; i < TOKENS * DIMT; i += 1024) {
            const int row = i >> 10, t = i & 1023;
            q_s[row * QK_STRIDE + t] = Q[base + i];
            k_s[row * QK_STRIDE + t] = Km[base + i];
        }
        if (tid < 256) { wl_s[tid] = Wl[tid]; ww_s[tid] = Ww[tid]; }
        else if (tid < 272) { bl_s[tid - 256] = bl[tid - 256]; }
        else if (tid < 288) { bw_s[tid - 272] = bw[tid - 272]; }
    }
    __syncthreads();

    // scores: one (h,n,m) per thread
    {
        const int h = tid >> 6, n = (tid >> 3) & 7, m = tid & 7;
        const float* qp = q_s + n * QK_STRIDE + h * HEADD;
        const float* kp = k_s + m * QK_STRIDE + h * HEADD;
        float dd = 0.0f;
        #pragma unroll
        for (int t = 0; t < HEADD; t++) dd += qp[t] * kp[t];
        s_s[h][n][m] = dd * ATT_SCALE;
    }
    __syncthreads();

    // talking-heads mix #1
    {
        const int g = tid >> 6, n = (tid >> 3) & 7, m = tid & 7;
        float acc = bl_s[g];
        #pragma unroll
        for (int h = 0; h < NHEADS; h++) acc += s_s[h][n][m] * wl_s[h * 16 + g];
        t_s[g][n][m] = acc;
    }
    __syncthreads();

    // softmax over m
    if (tid < 128) {
        const int g = tid >> 3, n = tid & 7;
        float mx = t_s[g][n][0];
        #pragma unroll
        for (int m = 1; m < TOKENS; m++) mx = fmaxf(mx, t_s[g][n][m]);
        float e[TOKENS], sum = 0.0f;
        #pragma unroll
        for (int m = 0; m < TOKENS; m++) { e[m] = expf(t_s[g][n][m] - mx); sum += e[m]; }
        const float inv = 1.0f / sum;
        #pragma unroll
        for (int m = 0; m < TOKENS; m++) t_s[g][n][m] = e[m] * inv;
    }
    __syncthreads();

    // talking-heads mix #2
    {
        const int g = tid >> 6, n = (tid >> 3) & 7, m = tid & 7;
        float acc = bw_s[g];
        #pragma unroll
        for (int h = 0; h < NHEADS; h++) acc += t_s[h][n][m] * ww_s[h * 16 + g];
        u_s[g][n][m] = acc;
    }
    __syncthreads();

    // o[n][c..c+3], c = 4*tid, head hh = tid >> 6 (constant within warp -> broadcast LDS)
    const int c0 = tid * 4;
    const int hh = tid >> 6;
    float4 acc4[TOKENS];
    #pragma unroll
    for (int n = 0; n < TOKENS; n++) acc4[n] = make_float4(0.f, 0.f, 0.f, 0.f);

    const float* Vb = V + rowbase * HIDT;
    #pragma unroll
    for (int m = 0; m < TOKENS; m++) {
        const float4 v4 = *(const float4*)(Vb + (long)m * HIDT + c0);
        #pragma unroll
        for (int n = 0; n < TOKENS; n++) {
            const float u = u_s[hh][n][m];
            acc4[n].x += u * v4.x;
            acc4[n].y += u * v4.y;
            acc4[n].z += u * v4.z;
            acc4[n].w += u * v4.w;
        }
    }

    // LayerNorm: mean via warp shuffle + 32-partial tree
    #pragma unroll
    for (int n = 0; n < TOKENS; n++) {
        float p = acc4[n].x + acc4[n].y + acc4[n].z + acc4[n].w;
        #pragma unroll
        for (int o = 16; o > 0; o >>= 1) p += __shfl_xor_sync(0xFFFFFFFF, p, o);
        if (lane == 0) red[n][wrp] = p;
    }
    __syncthreads();
    if (tid < TOKENS) {
        float s = 0.0f;
        #pragma unroll
        for (int w = 0; w < 32; w++) s += red[tid][w];
        mean_s[tid] = s * (1.0f / HIDT);
    }
    __syncthreads();
    // variance
    #pragma unroll
    for (int n = 0; n < TOKENS; n++) {
        const float mu = mean_s[n];
        const float dx = acc4[n].x - mu, dy = acc4[n].y - mu;
        const float dz = acc4[n].z - mu, dw = acc4[n].w - mu;
        float p = dx * dx + dy * dy + dz * dz + dw * dw;
        #pragma unroll
        for (int o = 16; o > 0; o >>= 1) p += __shfl_xor_sync(0xFFFFFFFF, p, o);
        if (lane == 0) red[n][wrp] = p;
    }
    __syncthreads();
    if (tid < TOKENS) {
        float s = 0.0f;
        #pragma unroll
        for (int w = 0; w < 32; w++) s += red[tid][w];
        rstd_s[tid] = rsqrtf(s * (1.0f / HIDT) + LN_EPS);
    }
    __syncthreads();

    // normalize + swish + store (gamma/beta hoisted: fixed columns per thread)
    const float4 g4 = *(const float4*)(gamma + c0);
    const float4 b4 = *(const float4*)(beta + c0);
    #pragma unroll
    for (int n = 0; n < TOKENS; n++) {
        const float mu = mean_s[n];
        const float rs = rstd_s[n];
        float4 y;
        y.x = (acc4[n].x - mu) * rs * g4.x + b4.x;
        y.y = (acc4[n].y - mu) * rs * g4.y + b4.y;
        y.z = (acc4[n].z - mu) * rs * g4.z + b4.z;
        y.w = (acc4[n].w - mu) * rs * g4.w + b4.w;
        y.x = y.x / (1.0f + expf(-y.x));
        y.y = y.y / (1.0f + expf(-y.y));
        y.z = y.z / (1.0f + expf(-y.z));
        y.w = y.w / (1.0f + expf(-y.w));
        *(float4*)(Aout + (rowbase + n) * HIDT + c0) = y;
    }
}

#define ATTN_SMEM (2 * TOKENS * QK_STRIDE * 4)   // 65792

// ---------------------------------------------------------------------------
// Launch
// ---------------------------------------------------------------------------
extern "C" void kernel_launch(void* const* d_in, const int* in_sizes, int n_in,
                              void* d_out, int out_size)
{
    const float* x     = (const float*)d_in[0];
    const float* Wq    = (const float*)d_in[1];
    const float* bq    = (const float*)d_in[2];
    const float* Wk    = (const float*)d_in[3];
    const float* bk    = (const float*)d_in[4];
    const float* Wv    = (const float*)d_in[5];
    const float* bv    = (const float*)d_in[6];
    const float* Wl    = (const float*)d_in[7];
    const float* bl    = (const float*)d_in[8];
    const float* Ww    = (const float*)d_in[9];
    const float* bw    = (const float*)d_in[10];
    const float* gamma = (const float*)d_in[11];
    const float* beta  = (const float*)d_in[12];
    const float* Wp    = (const float*)d_in[13];
    const float* bp    = (const float*)d_in[14];
    float* out = (float*)d_out;

    float *qb, *kb, *vb, *ab;
    cudaGetSymbolAddress((void**)&qb, g_Q);
    cudaGetSymbolAddress((void**)&kb, g_K);
    cudaGetSymbolAddress((void**)&vb, g_V);
    cudaGetSymbolAddress((void**)&ab, g_A);

    cudaFuncSetAttribute(gemm_tc, cudaFuncAttributeMaxDynamicSharedMemorySize, GEMM_SMEM);
    cudaFuncSetAttribute(attn_ln_kernel, cudaFuncAttributeMaxDynamicSharedMemorySize, ATTN_SMEM);

    gemm_tc<<<dim3(DIMT / GBN, MROWS / GBM), 256, GEMM_SMEM>>>(x, Wq, bq, qb, DIMT, DIMT);
    gemm_tc<<<dim3(DIMT / GBN, MROWS / GBM), 256, GEMM_SMEM>>>(x, Wk, bk, kb, DIMT, DIMT);
    gemm_tc<<<dim3(HIDT / GBN, MROWS / GBM), 256, GEMM_SMEM>>>(x, Wv, bv, vb, HIDT, DIMT);

    attn_ln_kernel<<<BATCH, 1024, ATTN_SMEM>>>(qb, kb, vb, Wl, bl, Ww, bw, gamma, beta, ab);

    gemm_tc<<<dim3(OUTT / GBN, MROWS / GBM), 256, GEMM_SMEM>>>(ab, Wp, bp, out, OUTT, HIDT);
}